// round 10
// baseline (speedup 1.0000x reference)
#include <cuda_runtime.h>
#include <cuda_bf16.h>
#include <cstdint>

// Problem constants
#define Mv 8192
#define Nv 8192
#define Cv 80

#define ZSPLIT 16                 // row interleave factor per class
#define ROWS_T 64                 // rows per vmat producer block
#define SPAD 81                   // smem row stride -> conflict-free column walks
#define NVMAT 128                 // vmat producer blocks (Nv / ROWS_T)
#define NPROD 129                 // + 1 group block
#define NSEG 8                    // 1024-column output segments
#define NCONS (NSEG * Cv * ZSPLIT)  // 10240 consumer blocks

// Scratch (no allocation allowed in kernel_launch)
__device__ float g_V[Cv][Nv];     // V[c][n] = base[n] - pc[n][c]
__device__ int   g_perm[Mv];
__device__ int   g_off[Cv + 1];

// Device-side gating state (zero-init at load; reset by last consumer each run)
__device__ volatile int g_seg_done[NSEG];   // 16 producers per segment
__device__ volatile int g_grp_done;
__device__ int          g_cons_done;

__global__ void __launch_bounds__(256, 8) fused_kernel(const float* __restrict__ pc,
                                                       const int* __restrict__ g,
                                                       float* __restrict__ out) {
    const int bid = blockIdx.x;
    const int t   = threadIdx.x;

    if (bid < NVMAT) {
        // ---------------- vmat producer: 64 rows, 4 threads per row ------
        __shared__ float sp[ROWS_T * SPAD];       // 20.7 KB tile
        __shared__ float sb[ROWS_T];

        const int n0 = bid * ROWS_T;

        // Load tile (64 rows x 80 floats = 1280 float4), coalesced.
        const float4* src = reinterpret_cast<const float4*>(pc + (size_t)n0 * Cv);
#pragma unroll
        for (int i = 0; i < 5; i++) {
            int q4 = i * 256 + t;
            float4 v = src[q4];
            int row = q4 / 20, c4 = q4 % 20;
            float* d = &sp[row * SPAD + c4 * 4];
            d[0] = v.x; d[1] = v.y; d[2] = v.z; d[3] = v.w;
        }
        __syncthreads();

        // 4 adjacent lanes per row: S = sum max(x,0); P = prod(1+e^{-|x|}).
        const int r = t >> 2;
        const int q = t & 3;
        float S = 0.0f, P = 1.0f;
#pragma unroll 5
        for (int j = 0; j < 20; j++) {
            float x = sp[r * SPAD + q * 20 + j];
            S += fmaxf(x, 0.0f);
            P *= 1.0f + __expf(-fabsf(x));
        }
        S += __shfl_xor_sync(0xFFFFFFFFu, S, 1);
        P *= __shfl_xor_sync(0xFFFFFFFFu, P, 1);
        S += __shfl_xor_sync(0xFFFFFFFFu, S, 2);
        P *= __shfl_xor_sync(0xFFFFFFFFu, P, 2);
        if (q == 0) sb[r] = S + __logf(P);        // one LG2 per row
        __syncthreads();

        // V[c][n0+rr] = base[rr] - x ; 64-float coalesced runs per c.
#pragma unroll 4
        for (int idx = t; idx < Cv * ROWS_T; idx += 256) {
            int c = idx >> 6, rr = idx & 63;
            g_V[c][n0 + rr] = sb[rr] - sp[rr * SPAD + c];
        }

        // Release this segment (16 producers per 1024-column segment).
        __threadfence();
        __syncthreads();
        if (t == 0) atomicAdd((int*)&g_seg_done[bid >> 4], 1);

    } else if (bid == NVMAT) {
        // ---------------- group producer: counting sort by class ---------
        __shared__ int cnt[Cv];
        __shared__ int offs[Cv + 1];
        if (t < Cv) cnt[t] = 0;
        __syncthreads();
        for (int m = t; m < Mv; m += 256)
            atomicAdd(&cnt[g[m]], 1);
        __syncthreads();
        if (t == 0) {
            int acc = 0;
            for (int c = 0; c < Cv; c++) { offs[c] = acc; acc += cnt[c]; }
            offs[Cv] = acc;
        }
        __syncthreads();
        if (t <= Cv) g_off[t] = offs[t];
        if (t < Cv)  cnt[t] = offs[t];            // reuse as cursor
        __syncthreads();
        for (int m = t; m < Mv; m += 256) {
            int pos = atomicAdd(&cnt[g[m]], 1);
            g_perm[pos] = m;
        }
        __threadfence();
        __syncthreads();
        if (t == 0) g_grp_done = 1;

    } else {
        // ---------------- consumer: stream V[c] slice to class rows ------
        const int lin = bid - NPROD;
        const int x   = lin & 7;                  // column segment (fastest)
        const int tcz = lin >> 3;
        const int c   = tcz % Cv;
        const int z   = tcz / Cv;

        // Gate on this segment's producers + the group block.
        if (t == 0) {
            while (g_seg_done[x] < 16 || g_grp_done == 0) __nanosleep(64);
            __threadfence();
        }
        __syncthreads();

        const int i0 = g_off[c];
        const int i1 = g_off[c + 1];
        if (i0 + z < i1) {
            const int n0 = x * 1024 + t * 4;
            const float4 v = *reinterpret_cast<const float4*>(&g_V[c][n0]);
            float4* out4 = reinterpret_cast<float4*>(out);
            const size_t col = (size_t)(n0 >> 2);
            for (int i = i0 + z; i < i1; i += ZSPLIT) {
                int m = g_perm[i];                              // broadcast load
                __stcs(&out4[(size_t)m * (Nv / 4) + col], v);   // streaming STG.128
            }
        }

        // Last consumer resets gating state for the next graph replay.
        __syncthreads();
        if (t == 0) {
            int done = atomicAdd(&g_cons_done, 1);
            if (done == NCONS - 1) {
                for (int s = 0; s < NSEG; s++) g_seg_done[s] = 0;
                g_grp_done  = 0;
                g_cons_done = 0;
            }
        }
    }
}

extern "C" void kernel_launch(void* const* d_in, const int* in_sizes, int n_in,
                              void* d_out, int out_size) {
    const int*   g;
    const float* pc;
    if (in_sizes[0] == Mv) {
        g  = (const int*)d_in[0];
        pc = (const float*)d_in[1];
    } else {
        g  = (const int*)d_in[1];
        pc = (const float*)d_in[0];
    }
    float* out = (float*)d_out;

    fused_kernel<<<NPROD + NCONS, 256>>>(pc, g, out);
}

// round 11
// speedup vs baseline: 1.1084x; 1.1084x over previous
#include <cuda_runtime.h>
#include <cuda_bf16.h>
#include <cstdint>

// Problem constants
#define Mv 8192
#define Nv 8192
#define Cv 80

#define ZSPLIT 16         // row interleave factor per class in write kernel
#define ROWS_T 64         // rows per vmat block
#define SPAD 81           // smem row stride -> conflict-free column walks

// Scratch (no allocation allowed in kernel_launch)
__device__ float g_V[Cv][Nv];     // V[c][n] = base[n] - pc[n][c]
__device__ int   g_perm[Mv];
__device__ int   g_off[Cv + 1];

// Fused phase 1: blocks 0..127 compute V; block 128 does the class grouping.
// blockDim = 256.
__global__ void __launch_bounds__(256) phase1_kernel(const float* __restrict__ pc,
                                                     const int* __restrict__ g) {
    if (blockIdx.x < 128) {
        // ---------------- vmat path: 64 rows, 4 threads per row ----------
        __shared__ float sp[ROWS_T * SPAD];       // 20.7 KB tile
        __shared__ float sS[ROWS_T][4];           // partial max-sums
        __shared__ float sP[ROWS_T][4];           // partial products
        __shared__ float sb[ROWS_T];              // base per row

        const int n0 = blockIdx.x * ROWS_T;
        const int t  = threadIdx.x;

        // Load tile (64 rows x 80 floats = 1280 float4), coalesced.
        const float4* src = reinterpret_cast<const float4*>(pc + (size_t)n0 * Cv);
#pragma unroll
        for (int i = 0; i < 5; i++) {
            int q4 = i * 256 + t;
            float4 v = src[q4];
            int row = q4 / 20, c4 = q4 % 20;
            float* d = &sp[row * SPAD + c4 * 4];
            d[0] = v.x; d[1] = v.y; d[2] = v.z; d[3] = v.w;
        }
        __syncthreads();

        // Each thread: 20 classes of one row. S = sum max(x,0); P = prod(1+e^{-|x|}).
        const int r = t & 63;
        const int q = t >> 6;
        float S = 0.0f, P = 1.0f;
#pragma unroll 5
        for (int j = 0; j < 20; j++) {
            float x = sp[r * SPAD + q * 20 + j];
            S += fmaxf(x, 0.0f);
            P *= 1.0f + __expf(-fabsf(x));
        }
        sS[r][q] = S;
        sP[r][q] = P;
        __syncthreads();

        // Rows reduce: base = sum(S) + log(prod(P))  -> one LG2 per row.
        if (t < ROWS_T) {
            float Ssum = sS[t][0] + sS[t][1] + sS[t][2] + sS[t][3];
            float Pprod = (sP[t][0] * sP[t][1]) * (sP[t][2] * sP[t][3]);
            sb[t] = Ssum + __logf(Pprod);
        }
        __syncthreads();

        // V[c][n0+r] = base[r] - x ; 64-float coalesced runs per c.
#pragma unroll 4
        for (int idx = t; idx < Cv * ROWS_T; idx += 256) {
            int c = idx >> 6, rr = idx & 63;
            g_V[c][n0 + rr] = sb[rr] - sp[rr * SPAD + c];
        }
    } else {
        // ---------------- group path: counting sort by class -------------
        __shared__ int cnt[Cv];
        __shared__ int offs[Cv + 1];
        int tid = threadIdx.x;
        if (tid < Cv) cnt[tid] = 0;
        __syncthreads();
        for (int m = tid; m < Mv; m += 256)
            atomicAdd(&cnt[g[m]], 1);
        __syncthreads();
        if (tid == 0) {
            int acc = 0;
            for (int c = 0; c < Cv; c++) { offs[c] = acc; acc += cnt[c]; }
            offs[Cv] = acc;
        }
        __syncthreads();
        if (tid <= Cv) g_off[tid] = offs[tid];
        if (tid < Cv)  cnt[tid] = offs[tid];   // reuse as cursor
        __syncthreads();
        for (int m = tid; m < Mv; m += 256) {
            int pos = atomicAdd(&cnt[g[m]], 1);
            g_perm[pos] = m;
        }
    }
}

// Write kernel: grid = (Nv/1024, Cv, ZSPLIT), block = 256.
// Setup = one coalesced 4KB read of V[c]; stream it to this block's
// interleaved subset of the class's output rows with evict-first stores.
__global__ void __launch_bounds__(256) write_kernel(float* __restrict__ out) {
    const int c  = blockIdx.y;
    const int z  = blockIdx.z;
    const int i0 = g_off[c];
    const int i1 = g_off[c + 1];
    if (i0 + z >= i1) return;

    const int n0 = (blockIdx.x * 256 + threadIdx.x) * 4;
    const float4 v = *reinterpret_cast<const float4*>(&g_V[c][n0]);

    float4* out4 = reinterpret_cast<float4*>(out);
    const size_t col = (size_t)(n0 >> 2);

    for (int i = i0 + z; i < i1; i += ZSPLIT) {
        int m = g_perm[i];                              // broadcast load
        __stcs(&out4[(size_t)m * (Nv / 4) + col], v);   // streaming STG.128
    }
}

extern "C" void kernel_launch(void* const* d_in, const int* in_sizes, int n_in,
                              void* d_out, int out_size) {
    const int*   g;
    const float* pc;
    if (in_sizes[0] == Mv) {
        g  = (const int*)d_in[0];
        pc = (const float*)d_in[1];
    } else {
        g  = (const int*)d_in[1];
        pc = (const float*)d_in[0];
    }
    float* out = (float*)d_out;

    phase1_kernel<<<129, 256>>>(pc, g);
    dim3 grid(Nv / 1024, Cv, ZSPLIT);
    write_kernel<<<grid, 256>>>(out);
}